// round 2
// baseline (speedup 1.0000x reference)
#include <cuda_runtime.h>
#include <math.h>

// Problem constants (match reference)
#define NGRAPH 128
#define FDIM   64
#define MAXN   100000
#define GEPS   1e-5f

// ---------------- device scratch (no allocations allowed) ----------------
__device__ float g_dinv[MAXN];
__device__ float g_cnt[NGRAPH];
__device__ float g_bufA[MAXN * FDIM];
__device__ float g_bufB[MAXN * FDIM];
__device__ float g_gsum[NGRAPH * FDIM];
__device__ float g_gsq[NGRAPH * FDIM];
__device__ float g_scale[NGRAPH * FDIM];
__device__ float g_shift[NGRAPH * FDIM];

// ---------------- helpers ----------------
__device__ __forceinline__ void red_add_v4(float* p, float4 v) {
    asm volatile("red.global.add.v4.f32 [%0], {%1,%2,%3,%4};"
                 :: "l"(p), "f"(v.x), "f"(v.y), "f"(v.z), "f"(v.w)
                 : "memory");
}

__device__ __forceinline__ float4 f4_fma_s(float4 a, float s, float4 b) {
    return make_float4(fmaf(a.x, s, b.x), fmaf(a.y, s, b.y),
                       fmaf(a.z, s, b.z), fmaf(a.w, s, b.w));
}

// ---------------- init: dinv=1, cnt=0, stats=0, out=0 ----------------
__global__ void k_init(float* out, int N) {
    int i = blockIdx.x * blockDim.x + threadIdx.x;
    if (i < N) g_dinv[i] = 1.0f;
    if (i < NGRAPH) g_cnt[i] = 0.0f;
    if (i < NGRAPH * FDIM) {
        g_gsum[i] = 0.0f;
        g_gsq[i]  = 0.0f;
        out[i]    = 0.0f;
    }
}

__global__ void k_deg(const int* __restrict__ dst, int E) {
    int i = blockIdx.x * blockDim.x + threadIdx.x;
    if (i < E) atomicAdd(&g_dinv[dst[i]], 1.0f);
}

__global__ void k_cnt(const int* __restrict__ batch, int N) {
    int i = blockIdx.x * blockDim.x + threadIdx.x;
    if (i < N) atomicAdd(&g_cnt[batch[i]], 1.0f);
}

__global__ void k_rsqrt(int N) {
    int i = blockIdx.x * blockDim.x + threadIdx.x;
    if (i < N) g_dinv[i] = rsqrtf(g_dinv[i]);
}

// ---------------- GEMM: out[r,:] = (X[r,:] @ W) * dinv[r] ----------------
// Block tile 64 rows x 64 cols, 256 threads, each thread 4x4 micro-tile.
template<int K>
__global__ __launch_bounds__(256)
void k_gemm_scale(const float* __restrict__ X, const float* __restrict__ W,
                  float* __restrict__ out, int N) {
    __shared__ float Ws[K][FDIM];
    __shared__ float Xs[64][17];

    int tid = threadIdx.x;
    for (int i = tid; i < K * FDIM; i += 256)
        Ws[i / FDIM][i % FDIM] = W[i];

    int rowBase = blockIdx.x * 64;
    int ty = tid / 16;   // 0..15 -> row group of 4
    int tx = tid % 16;   // 0..15 -> col group of 4

    float acc[4][4] = {};

    for (int kc = 0; kc < K; kc += 16) {
        __syncthreads();  // Ws ready on first iter; Xs safe to overwrite after
        for (int i = tid; i < 64 * 16; i += 256) {
            int m = i / 16, k = i % 16;
            int r = rowBase + m;
            Xs[m][k] = (r < N) ? X[(size_t)r * K + kc + k] : 0.0f;
        }
        __syncthreads();
        #pragma unroll
        for (int k = 0; k < 16; ++k) {
            const float4 wf = *(const float4*)(&Ws[kc + k][tx * 4]);
            float xv[4];
            #pragma unroll
            for (int i = 0; i < 4; ++i) xv[i] = Xs[ty * 4 + i][k];
            #pragma unroll
            for (int i = 0; i < 4; ++i) {
                acc[i][0] = fmaf(xv[i], wf.x, acc[i][0]);
                acc[i][1] = fmaf(xv[i], wf.y, acc[i][1]);
                acc[i][2] = fmaf(xv[i], wf.z, acc[i][2]);
                acc[i][3] = fmaf(xv[i], wf.w, acc[i][3]);
            }
        }
    }

    #pragma unroll
    for (int i = 0; i < 4; ++i) {
        int r = rowBase + ty * 4 + i;
        if (r < N) {
            float s = g_dinv[r];
            float4 v = make_float4(acc[i][0] * s, acc[i][1] * s,
                                   acc[i][2] * s, acc[i][3] * s);
            *(float4*)&out[(size_t)r * FDIM + tx * 4] = v;
        }
    }
}

// ---------------- copy (self-loop init): dstbuf = srcbuf ----------------
__global__ void k_copy(float4* __restrict__ d, const float4* __restrict__ s, int n16) {
    int i = blockIdx.x * blockDim.x + threadIdx.x;
    if (i < n16) d[i] = s[i];
}

// ---------------- edge scatter: hout[dst] += hin[src] (float4 chunks) ----
__global__ void k_scatter(const int* __restrict__ src, const int* __restrict__ dst,
                          const float* __restrict__ hin, float* __restrict__ hout, int E) {
    int t = blockIdx.x * blockDim.x + threadIdx.x;
    if (t >= E * 16) return;
    int e = t >> 4;
    int c = t & 15;
    int s = __ldg(&src[e]);
    int d = __ldg(&dst[e]);
    float4 v = *(const float4*)(hin + (size_t)s * FDIM + c * 4);
    red_add_v4(hout + (size_t)d * FDIM + c * 4, v);
}

// ---------------- finish conv + accumulate graph stats -------------------
// buf = buf*dinv + b ; gsum += buf ; gsq += buf*buf
__global__ void k_finish(float* __restrict__ buf, const float* __restrict__ bvec,
                         const int* __restrict__ batch, int N) {
    int t = blockIdx.x * blockDim.x + threadIdx.x;
    if (t >= N * 16) return;
    int i = t >> 4;
    int c = t & 15;
    float s = g_dinv[i];
    float4* p = (float4*)buf + t;
    float4 b = *(const float4*)(bvec + c * 4);
    float4 v = f4_fma_s(*p, s, b);
    *p = v;
    int g = batch[i];
    red_add_v4(&g_gsum[g * FDIM + c * 4], v);
    float4 v2 = make_float4(v.x * v.x, v.y * v.y, v.z * v.z, v.w * v.w);
    red_add_v4(&g_gsq[g * FDIM + c * 4], v2);
}

// ---------------- per-(graph,feature) scale/shift for GraphNorm ----------
// out = w*(x - a*mean)*istd + bias  ==>  x*scale + shift
__global__ void k_stats(const float* __restrict__ alpha, const float* __restrict__ weight,
                        const float* __restrict__ bias) {
    int t = blockIdx.x * blockDim.x + threadIdx.x;
    if (t >= NGRAPH * FDIM) return;
    int g = t / FDIM, f = t % FDIM;
    float c = fmaxf(g_cnt[g], 1.0f);
    float mean = g_gsum[t] / c;
    float ex2  = g_gsq[t] / c;
    float a = alpha[f];
    float var = ex2 - (2.0f * a - a * a) * mean * mean;
    float istd = rsqrtf(var + GEPS);
    float sc = weight[f] * istd;
    g_scale[t] = sc;
    g_shift[t] = bias[f] - a * mean * sc;
}

__global__ void k_zero_stats() {
    int t = blockIdx.x * blockDim.x + threadIdx.x;
    if (t < NGRAPH * FDIM) { g_gsum[t] = 0.0f; g_gsq[t] = 0.0f; }
}

// ---------------- apply norm + relu -> out buffer ------------------------
__global__ void k_apply(const float* __restrict__ in, float* __restrict__ out,
                        const int* __restrict__ batch, int N) {
    int t = blockIdx.x * blockDim.x + threadIdx.x;
    if (t >= N * 16) return;
    int i = t >> 4;
    int c = t & 15;
    int g = batch[i];
    float4 sc = *(const float4*)&g_scale[g * FDIM + c * 4];
    float4 sh = *(const float4*)&g_shift[g * FDIM + c * 4];
    float4 v = *((const float4*)in + t);
    float4 r = make_float4(fmaxf(fmaf(v.x, sc.x, sh.x), 0.0f),
                           fmaxf(fmaf(v.y, sc.y, sh.y), 0.0f),
                           fmaxf(fmaf(v.z, sc.z, sh.z), 0.0f),
                           fmaxf(fmaf(v.w, sc.w, sh.w), 0.0f));
    *((float4*)out + t) = r;
}

// ---------------- apply norm + relu + mean-pool accumulate ---------------
__global__ void k_apply_pool(const float* __restrict__ in, float* __restrict__ dout,
                             const int* __restrict__ batch, int N) {
    int t = blockIdx.x * blockDim.x + threadIdx.x;
    if (t >= N * 16) return;
    int i = t >> 4;
    int c = t & 15;
    int g = batch[i];
    float4 sc = *(const float4*)&g_scale[g * FDIM + c * 4];
    float4 sh = *(const float4*)&g_shift[g * FDIM + c * 4];
    float4 v = *((const float4*)in + t);
    float4 r = make_float4(fmaxf(fmaf(v.x, sc.x, sh.x), 0.0f),
                           fmaxf(fmaf(v.y, sc.y, sh.y), 0.0f),
                           fmaxf(fmaf(v.z, sc.z, sh.z), 0.0f),
                           fmaxf(fmaf(v.w, sc.w, sh.w), 0.0f));
    red_add_v4(dout + g * FDIM + c * 4, r);
}

__global__ void k_div(float* __restrict__ dout) {
    int t = blockIdx.x * blockDim.x + threadIdx.x;
    if (t >= NGRAPH * FDIM) return;
    dout[t] *= 1.0f / fmaxf(g_cnt[t / FDIM], 1.0f);
}

// ---------------- launcher ----------------
extern "C" void kernel_launch(void* const* d_in, const int* in_sizes, int n_in,
                              void* d_out, int out_size) {
    const float* x      = (const float*)d_in[0];
    const int*   ei     = (const int*)  d_in[1];
    const int*   batch  = (const int*)  d_in[2];
    const float* W1     = (const float*)d_in[3];
    const float* b1     = (const float*)d_in[4];
    const float* alpha1 = (const float*)d_in[5];
    const float* weight1= (const float*)d_in[6];
    const float* bias1  = (const float*)d_in[7];
    const float* W2     = (const float*)d_in[8];
    const float* b2     = (const float*)d_in[9];
    const float* alpha2 = (const float*)d_in[10];
    const float* weight2= (const float*)d_in[11];
    const float* bias2  = (const float*)d_in[12];
    float* out = (float*)d_out;

    int N = in_sizes[2];
    int E = in_sizes[1] / 2;
    const int* src = ei;
    const int* dst = ei + E;

    float *pA, *pB;
    cudaGetSymbolAddress((void**)&pA, g_bufA);
    cudaGetSymbolAddress((void**)&pB, g_bufB);

    const int T = 256;
    int nbN   = (N + T - 1) / T;
    int nbE   = (E + T - 1) / T;
    int nb16  = (N * 16 + T - 1) / T;
    int nbE16 = (E * 16 + T - 1) / T;
    int nbGF  = (NGRAPH * FDIM + T - 1) / T;
    int nbRow = (N + 63) / 64;

    // degrees, counts
    k_init <<<nbN, T>>>(out, N);
    k_deg  <<<nbE, T>>>(dst, E);
    k_cnt  <<<nbN, T>>>(batch, N);
    k_rsqrt<<<nbN, T>>>(N);

    // ---- layer 1 ----
    k_gemm_scale<128><<<nbRow, T>>>(x, W1, pA, N);           // hs = (x@W1)*dinv
    k_copy   <<<nb16, T>>>((float4*)pB, (const float4*)pA, N * 16);  // self loop
    k_scatter<<<nbE16, T>>>(src, dst, pA, pB, E);
    k_finish <<<nb16, T>>>(pB, b1, batch, N);                // *dinv + b1, stats
    k_stats  <<<nbGF, T>>>(alpha1, weight1, bias1);
    k_apply  <<<nb16, T>>>(pB, pA, batch, N);                // norm+relu -> A
    k_zero_stats<<<nbGF, T>>>();

    // ---- layer 2 ----
    k_gemm_scale<64><<<nbRow, T>>>(pA, W2, pB, N);           // hs2 = (h@W2)*dinv
    k_copy   <<<nb16, T>>>((float4*)pA, (const float4*)pB, N * 16);
    k_scatter<<<nbE16, T>>>(src, dst, pB, pA, E);
    k_finish <<<nb16, T>>>(pA, b2, batch, N);
    k_stats  <<<nbGF, T>>>(alpha2, weight2, bias2);
    k_apply_pool<<<nb16, T>>>(pA, out, batch, N);            // norm+relu+pool
    k_div    <<<nbGF, T>>>(out);
}

// round 6
// speedup vs baseline: 1.2545x; 1.2545x over previous
#include <cuda_runtime.h>
#include <math.h>

#define NGRAPH 128
#define FDIM   64
#define MAXN   100000
#define MAXE   1600000
#define GEPS   1e-5f

// ---------------- device scratch ----------------
__device__ float g_dinv[MAXN];
__device__ float g_cnt[NGRAPH];
__device__ float g_cinv[NGRAPH];
__device__ float g_bufA[MAXN * FDIM];
__device__ float g_bufB[MAXN * FDIM];
__device__ float g_gsum[NGRAPH * FDIM];
__device__ float g_gsq[NGRAPH * FDIM];
__device__ float g_scale[NGRAPH * FDIM];
__device__ float g_shift[NGRAPH * FDIM];
__device__ int   g_indeg[MAXN];
__device__ int   g_off[MAXN];
__device__ int   g_cursor[MAXN];
__device__ int   g_csr[MAXE];
__device__ int   g_bsum[512];
__device__ int   g_boff[512];

// ---------------- helpers ----------------
__device__ __forceinline__ void red_add_v2(float* p, float2 v) {
    asm volatile("red.global.add.v2.f32 [%0], {%1,%2};"
                 :: "l"(p), "f"(v.x), "f"(v.y) : "memory");
}
__device__ __forceinline__ void red_add_v4(float* p, float4 v) {
    asm volatile("red.global.add.v4.f32 [%0], {%1,%2,%3,%4};"
                 :: "l"(p), "f"(v.x), "f"(v.y), "f"(v.z), "f"(v.w) : "memory");
}

// ---------------- init ----------------
__global__ void k_init(float* out, int N) {
    int i = blockIdx.x * blockDim.x + threadIdx.x;
    if (i < N) g_indeg[i] = 0;
    if (i < NGRAPH) g_cnt[i] = 0.0f;
    if (i < NGRAPH * FDIM) {
        g_gsum[i] = 0.0f;
        g_gsq[i]  = 0.0f;
        out[i]    = 0.0f;
    }
}

__global__ void k_deg(const int* __restrict__ dst, int E) {
    int i = blockIdx.x * blockDim.x + threadIdx.x;
    if (i < E) atomicAdd(&g_indeg[dst[i]], 1);
}

// ---------------- 3-kernel exclusive scan of indeg ----------------
__global__ void k_scan1(int N) {
    int t = threadIdx.x;
    int i = blockIdx.x * 256 + t;
    int v = (i < N) ? g_indeg[i] : 0;
    __shared__ int s[256];
    s[t] = v; __syncthreads();
    for (int d = 128; d > 0; d >>= 1) {
        if (t < d) s[t] += s[t + d];
        __syncthreads();
    }
    if (t == 0) g_bsum[blockIdx.x] = s[0];
}

__global__ void k_scan2(int nb) {
    __shared__ int s[512];
    int t = threadIdx.x;
    int v = (t < nb) ? g_bsum[t] : 0;
    s[t] = v; __syncthreads();
    for (int d = 1; d < 512; d <<= 1) {
        int x = (t >= d) ? s[t - d] : 0;
        __syncthreads();
        s[t] += x;
        __syncthreads();
    }
    if (t < nb) g_boff[t] = s[t] - v;  // exclusive
}

__global__ void k_scan3(const int* __restrict__ batch, int N) {
    int t = threadIdx.x;
    int i = blockIdx.x * 256 + t;
    int v = (i < N) ? g_indeg[i] : 0;
    __shared__ int s[256];
    s[t] = v; __syncthreads();
    for (int d = 1; d < 256; d <<= 1) {
        int x = (t >= d) ? s[t - d] : 0;
        __syncthreads();
        s[t] += x;
        __syncthreads();
    }
    int excl = s[t] - v + g_boff[blockIdx.x];
    if (i < N) {
        g_off[i]    = excl;
        g_cursor[i] = excl;
        g_dinv[i]   = rsqrtf((float)(v + 1));   // +1 self loop
        atomicAdd(&g_cnt[batch[i]], 1.0f);
    }
}

__global__ void k_fill(const int* __restrict__ src, const int* __restrict__ dst, int E) {
    int i = blockIdx.x * blockDim.x + threadIdx.x;
    if (i < E) {
        int pos = atomicAdd(&g_cursor[dst[i]], 1);
        g_csr[pos] = src[i];
    }
}

// ---------------- GEMM: out[r,:] = (f(X[r,:]) @ W) * dinv[r] ----------------
// FUSE: f = relu(x*scale+shift) per (batch[r], feature)
template<int K, bool FUSE>
__global__ __launch_bounds__(256)
void k_gemm_scale(const float* __restrict__ X, const float* __restrict__ W,
                  float* __restrict__ out, const int* __restrict__ batch, int N) {
    __shared__ float Ws[K][FDIM];
    __shared__ float Xs[64][17];
    __shared__ int   bs[64];

    int tid = threadIdx.x;
    int rowBase = blockIdx.x * 64;
    for (int i = tid; i < K * FDIM; i += 256)
        Ws[i / FDIM][i % FDIM] = W[i];
    if (FUSE && tid < 64) {
        int r = rowBase + tid;
        bs[tid] = (r < N) ? batch[r] : 0;
    }

    int ty = tid / 16;
    int tx = tid % 16;
    float acc[4][4] = {};

    for (int kc = 0; kc < K; kc += 16) {
        __syncthreads();
        for (int i = tid; i < 64 * 16; i += 256) {
            int m = i / 16, k = i % 16;
            int r = rowBase + m;
            float val = 0.0f;
            if (r < N) {
                int f = kc + k;
                val = X[(size_t)r * K + f];
                if (FUSE) {
                    int g = bs[m];
                    val = fmaxf(fmaf(val, g_scale[g * FDIM + f], g_shift[g * FDIM + f]), 0.0f);
                }
            }
            Xs[m][k] = val;
        }
        __syncthreads();
        #pragma unroll
        for (int k = 0; k < 16; ++k) {
            const float4 wf = *(const float4*)(&Ws[kc + k][tx * 4]);
            float xv[4];
            #pragma unroll
            for (int i = 0; i < 4; ++i) xv[i] = Xs[ty * 4 + i][k];
            #pragma unroll
            for (int i = 0; i < 4; ++i) {
                acc[i][0] = fmaf(xv[i], wf.x, acc[i][0]);
                acc[i][1] = fmaf(xv[i], wf.y, acc[i][1]);
                acc[i][2] = fmaf(xv[i], wf.z, acc[i][2]);
                acc[i][3] = fmaf(xv[i], wf.w, acc[i][3]);
            }
        }
    }

    #pragma unroll
    for (int i = 0; i < 4; ++i) {
        int r = rowBase + ty * 4 + i;
        if (r < N) {
            float s = g_dinv[r];
            float4 v = make_float4(acc[i][0] * s, acc[i][1] * s,
                                   acc[i][2] * s, acc[i][3] * s);
            *(float4*)&out[(size_t)r * FDIM + tx * 4] = v;
        }
    }
}

// ---------------- gather + conv epilogue + graph stats -------------------
// B[d] = (A[d] + sum_{s in nbr(d)} A[s]) * dinv[d] + b ; gsum += ; gsq +=
__global__ __launch_bounds__(256)
void k_gather(const float* __restrict__ A, float* __restrict__ B,
              const float* __restrict__ bvec, const int* __restrict__ batch, int N) {
    int warp = (blockIdx.x * blockDim.x + threadIdx.x) >> 5;
    int lane = threadIdx.x & 31;
    if (warp >= N) return;

    int start = g_off[warp];
    int deg   = g_indeg[warp];
    int end   = start + deg;
    size_t fo = (size_t)lane * 2;

    float dinv = g_dinv[warp];               // hoisted: overlap with loop
    float2 b   = *(const float2*)(bvec + fo);
    int    g   = batch[warp];

    float2 a0 = *(const float2*)(A + (size_t)warp * FDIM + fo);  // self
    float2 a1 = make_float2(0.f, 0.f);
    float2 a2 = make_float2(0.f, 0.f);
    float2 a3 = make_float2(0.f, 0.f);

    int j = start;
    for (; j + 4 <= end; j += 4) {
        int s0 = __ldg(&g_csr[j]);
        int s1 = __ldg(&g_csr[j + 1]);
        int s2 = __ldg(&g_csr[j + 2]);
        int s3 = __ldg(&g_csr[j + 3]);
        float2 v0 = *(const float2*)(A + (size_t)s0 * FDIM + fo);
        float2 v1 = *(const float2*)(A + (size_t)s1 * FDIM + fo);
        float2 v2 = *(const float2*)(A + (size_t)s2 * FDIM + fo);
        float2 v3 = *(const float2*)(A + (size_t)s3 * FDIM + fo);
        a0.x += v0.x; a0.y += v0.y;
        a1.x += v1.x; a1.y += v1.y;
        a2.x += v2.x; a2.y += v2.y;
        a3.x += v3.x; a3.y += v3.y;
    }
    for (; j < end; ++j) {
        int s0 = __ldg(&g_csr[j]);
        float2 v0 = *(const float2*)(A + (size_t)s0 * FDIM + fo);
        a0.x += v0.x; a0.y += v0.y;
    }

    float2 v;
    v.x = fmaf(a0.x + a1.x + a2.x + a3.x, dinv, b.x);
    v.y = fmaf(a0.y + a1.y + a2.y + a3.y, dinv, b.y);
    *(float2*)(B + (size_t)warp * FDIM + fo) = v;

    red_add_v2(&g_gsum[g * FDIM + (int)fo], v);
    red_add_v2(&g_gsq [g * FDIM + (int)fo], make_float2(v.x * v.x, v.y * v.y));
}

// ---------------- per-(graph,feature) scale/shift; resets stats ----------
__global__ void k_stats(const float* __restrict__ alpha, const float* __restrict__ weight,
                        const float* __restrict__ bias) {
    int t = blockIdx.x * blockDim.x + threadIdx.x;
    if (t >= NGRAPH * FDIM) return;
    int g = t / FDIM, f = t % FDIM;
    float c = fmaxf(g_cnt[g], 1.0f);
    float mean = g_gsum[t] / c;
    float ex2  = g_gsq[t] / c;
    float a = alpha[f];
    float var = ex2 - (2.0f * a - a * a) * mean * mean;
    float istd = rsqrtf(var + GEPS);
    float sc = weight[f] * istd;
    g_scale[t] = sc;
    g_shift[t] = bias[f] - a * mean * sc;
    g_gsum[t] = 0.0f;   // reset for next layer
    g_gsq[t]  = 0.0f;
    if (t < NGRAPH) g_cinv[t] = 1.0f / fmaxf(g_cnt[t], 1.0f);
}

// ---------------- norm + relu + mean-pool (1/cnt folded in) --------------
__global__ void k_apply_pool(const float* __restrict__ in, float* __restrict__ dout,
                             const int* __restrict__ batch, int N) {
    int t = blockIdx.x * blockDim.x + threadIdx.x;
    if (t >= N * 16) return;
    int i = t >> 4;
    int c = t & 15;
    int g = batch[i];
    float ci = g_cinv[g];
    float4 sc = *(const float4*)&g_scale[g * FDIM + c * 4];
    float4 sh = *(const float4*)&g_shift[g * FDIM + c * 4];
    float4 v = *((const float4*)in + t);
    float4 r = make_float4(fmaxf(fmaf(v.x, sc.x, sh.x), 0.0f) * ci,
                           fmaxf(fmaf(v.y, sc.y, sh.y), 0.0f) * ci,
                           fmaxf(fmaf(v.z, sc.z, sh.z), 0.0f) * ci,
                           fmaxf(fmaf(v.w, sc.w, sh.w), 0.0f) * ci);
    red_add_v4(dout + g * FDIM + c * 4, r);
}

// ---------------- launcher ----------------
extern "C" void kernel_launch(void* const* d_in, const int* in_sizes, int n_in,
                              void* d_out, int out_size) {
    const float* x      = (const float*)d_in[0];
    const int*   ei     = (const int*)  d_in[1];
    const int*   batch  = (const int*)  d_in[2];
    const float* W1     = (const float*)d_in[3];
    const float* b1     = (const float*)d_in[4];
    const float* alpha1 = (const float*)d_in[5];
    const float* weight1= (const float*)d_in[6];
    const float* bias1  = (const float*)d_in[7];
    const float* W2     = (const float*)d_in[8];
    const float* b2     = (const float*)d_in[9];
    const float* alpha2 = (const float*)d_in[10];
    const float* weight2= (const float*)d_in[11];
    const float* bias2  = (const float*)d_in[12];
    float* out = (float*)d_out;

    int N = in_sizes[2];
    int E = in_sizes[1] / 2;
    const int* src = ei;
    const int* dst = ei + E;

    float *pA, *pB;
    cudaGetSymbolAddress((void**)&pA, g_bufA);
    cudaGetSymbolAddress((void**)&pB, g_bufB);

    const int T = 256;
    int nbN    = (N + T - 1) / T;
    int nbE    = (E + T - 1) / T;
    int nb16   = (N * 16 + T - 1) / T;
    int nbGF   = (NGRAPH * FDIM + T - 1) / T;
    int nbRow  = (N + 63) / 64;
    int nbWarp = (N * 32 + T - 1) / T;

    // preprocess: degrees -> CSR
    k_init <<<nbN, T>>>(out, N);
    k_deg  <<<nbE, T>>>(dst, E);
    k_scan1<<<nbN, T>>>(N);
    k_scan2<<<1, 512>>>(nbN);
    k_scan3<<<nbN, T>>>(batch, N);
    k_fill <<<nbE, T>>>(src, dst, E);

    // ---- layer 1 ----
    k_gemm_scale<128, false><<<nbRow, T>>>(x, W1, pA, batch, N);
    k_gather<<<nbWarp, T>>>(pA, pB, b1, batch, N);
    k_stats <<<nbGF, T>>>(alpha1, weight1, bias1);

    // ---- layer 2 (norm+relu fused into gemm load) ----
    k_gemm_scale<64, true><<<nbRow, T>>>(pB, W2, pA, batch, N);
    k_gather<<<nbWarp, T>>>(pA, pB, b2, batch, N);
    k_stats <<<nbGF, T>>>(alpha2, weight2, bias2);

    // ---- pool (1/cnt folded into accumulation) ----
    k_apply_pool<<<nb16, T>>>(pB, out, batch, N);
}